// round 2
// baseline (speedup 1.0000x reference)
#include <cuda_runtime.h>

// FeatureFuser: out = sigmoid( last-write-wins(sampling_map, refined[k] over window_k) )
// B=8, TOP_K=4, C=32, H=W=256, GRID=4 (cell 64x64), WINDOW=3 cells (192x192, clipped).
//
// Per output pixel, exactly one source is read: refined[b, k_win, c, h, w] where
// k_win = max k whose window contains (h,w), else sampling_map[b,c,h,w].
// Window x-bounds are multiples of 64 -> uniform across an aligned float4.
//
// NOTE: reference requests int64 regions but JAX x64 is disabled -> int32 on device.

#define B_    8
#define K_    4
#define C_    32
#define H_    256
#define W_    256
#define W4_   (W_/4)

__global__ void __launch_bounds__(256, 8)
feature_fuser_kernel(const float* __restrict__ smap,
                     const float* __restrict__ rmap,
                     const int* __restrict__ regions,
                     float* __restrict__ out)
{
    int idx = blockIdx.x * blockDim.x + threadIdx.x;   // float4 index
    int w4 = idx & (W4_ - 1);
    int h  = (idx >> 6) & (H_ - 1);
    int bc = idx >> 14;            // b*C + c
    int c  = bc & (C_ - 1);
    int b  = bc >> 5;
    int w  = w4 << 2;

    // Find winning k: highest k whose window contains (h, w).
    int win = -1;
    #pragma unroll
    for (int k = K_ - 1; k >= 0; --k) {
        int ys = __ldg(&regions[(b * K_ + k) * 2 + 0]) << 6;
        int xs = __ldg(&regions[(b * K_ + k) * 2 + 1]) << 6;
        int ye = min(ys + 192, H_);
        int xe = min(xs + 192, W_);
        bool inside = (h >= ys) && (h < ye) && (w >= xs) && (w < xe);
        if (win < 0 && inside) win = k;
    }

    const float4* src;
    long row = (long)h * W_;
    if (win >= 0) {
        long off = ((((long)b * K_ + win) * C_ + c) * (long)(H_ * W_)) + row;
        src = reinterpret_cast<const float4*>(rmap + off) + w4;
    } else {
        long off = ((long)bc * (long)(H_ * W_)) + row;
        src = reinterpret_cast<const float4*>(smap + off) + w4;
    }

    float4 v = __ldg(src);

    // sigmoid(x) = 1 / (1 + exp(-x))
    v.x = __frcp_rn(1.0f + __expf(-v.x));
    v.y = __frcp_rn(1.0f + __expf(-v.y));
    v.z = __frcp_rn(1.0f + __expf(-v.z));
    v.w = __frcp_rn(1.0f + __expf(-v.w));

    reinterpret_cast<float4*>(out)[idx] = v;
}

extern "C" void kernel_launch(void* const* d_in, const int* in_sizes, int n_in,
                              void* d_out, int out_size)
{
    const float* smap    = (const float*)d_in[0];
    const float* rmap    = (const float*)d_in[1];
    const int*   regions = (const int*)d_in[2];
    float*       out     = (float*)d_out;

    const int total4 = B_ * C_ * H_ * W_ / 4;   // 4,194,304
    const int threads = 256;
    const int blocks = total4 / threads;        // 16384
    feature_fuser_kernel<<<blocks, threads>>>(smap, rmap, regions, out);
}

// round 3
// speedup vs baseline: 1.0598x; 1.0598x over previous
#include <cuda_runtime.h>

// FeatureFuser: out = sigmoid( last-write-wins(sampling_map, refined[k] over window_k) )
// B=8, TOP_K=4, C=32, H=W=256, GRID=4 (cell 64x64), WINDOW=3 cells (192x192, clipped).
//
// Per output pixel exactly one source is read: refined[b, k_win, c, h, w] where
// k_win = max k whose window contains (h,w), else sampling_map[b,c,h,w].
// Window x-bounds are multiples of 64 floats; each thread's 16 consecutive
// floats (16-aligned) therefore share a single winning k.
//
// regions arrive as int32 (JAX x64 disabled downcasts the int64 request).

#define B_    8
#define K_    4
#define C_    32
#define H_    256
#define W_    256
#define W4_   (W_/4)
#define V_    4           // float4s per thread

__device__ __forceinline__ float fast_sigmoid(float x) {
    // sigmoid(x) = 0.5*tanh(0.5*x) + 0.5  (MUFU.TANH)
    float t;
    asm("tanh.approx.f32 %0, %1;" : "=f"(t) : "f"(0.5f * x));
    return fmaf(0.5f, t, 0.5f);
}

__global__ void __launch_bounds__(256, 8)
feature_fuser_kernel(const float* __restrict__ smap,
                     const float* __restrict__ rmap,
                     const int* __restrict__ regions,
                     float* __restrict__ out)
{
    int t = blockIdx.x * blockDim.x + threadIdx.x;
    int base4 = t * V_;                    // first float4 index (4 consecutive, same row/cell)
    int w4 = base4 & (W4_ - 1);
    int h  = (base4 >> 6) & (H_ - 1);
    int bc = base4 >> 14;                  // b*C + c (constant across the 4 float4s)
    int c  = bc & (C_ - 1);
    int b  = bc >> 5;
    int w  = w4 << 2;

    // Winning k: highest k whose window contains (h, w). Uniform for all 4 float4s.
    int win = -1;
    #pragma unroll
    for (int k = K_ - 1; k >= 0; --k) {
        int ys = __ldg(&regions[(b * K_ + k) * 2 + 0]) << 6;
        int xs = __ldg(&regions[(b * K_ + k) * 2 + 1]) << 6;
        bool inside = (h >= ys) && (h < min(ys + 192, H_)) &&
                      (w >= xs) && (w < min(xs + 192, W_));
        if (win < 0 && inside) win = k;
    }

    long row = (long)h * W_;
    long off = (win >= 0)
        ? ((((long)b * K_ + win) * C_ + c) * (long)(H_ * W_)) + row
        : ((long)bc * (long)(H_ * W_)) + row;
    const float4* src = reinterpret_cast<const float4*>(
        (win >= 0 ? rmap : smap) + off) + w4;

    float4 v[V_];
    #pragma unroll
    for (int i = 0; i < V_; ++i) v[i] = __ldg(&src[i]);   // MLP=4

    #pragma unroll
    for (int i = 0; i < V_; ++i) {
        v[i].x = fast_sigmoid(v[i].x);
        v[i].y = fast_sigmoid(v[i].y);
        v[i].z = fast_sigmoid(v[i].z);
        v[i].w = fast_sigmoid(v[i].w);
    }

    float4* dst = reinterpret_cast<float4*>(out) + base4;
    #pragma unroll
    for (int i = 0; i < V_; ++i) dst[i] = v[i];
}

extern "C" void kernel_launch(void* const* d_in, const int* in_sizes, int n_in,
                              void* d_out, int out_size)
{
    const float* smap    = (const float*)d_in[0];
    const float* rmap    = (const float*)d_in[1];
    const int*   regions = (const int*)d_in[2];
    float*       out     = (float*)d_out;

    const int total4  = B_ * C_ * H_ * W_ / 4;       // 4,194,304 float4s
    const int threads = 256;
    const int blocks  = total4 / (threads * V_);     // 4096
    feature_fuser_kernel<<<blocks, threads>>>(smap, rmap, regions, out);
}